// round 2
// baseline (speedup 1.0000x reference)
#include <cuda_runtime.h>
#include <cstdint>
#include <cstddef>

#define BATCH 32
#define CIN   256
#define HW    3136
#define WIMG  56
#define NTOK  49
#define OCH   768
#define SIN   769   // smem row stride (odd -> conflict-free)

// Scratch: conv output, pixel-major [b][p][o] ; o: 0..511 = qk, 512..767 = v(relu)
__device__ float g_buf[(size_t)BATCH * HW * OCH];

// ---------------------------------------------------------------------------
// Kernel 1: fused 1x1 convs as GEMM  C[768,3136] = W[768,256] @ X[256,3136]
// ---------------------------------------------------------------------------
__global__ __launch_bounds__(256) void conv_kernel(
    const float* __restrict__ x,
    const float* __restrict__ qk_w,
    const float* __restrict__ v_w)
{
    const int b  = blockIdx.z;
    const int m0 = blockIdx.y * 128;
    const int n0 = blockIdx.x * 128;

    __shared__ float As[8][128];
    __shared__ float Bs[8][128];

    const int tid = threadIdx.x;
    const int tx = tid & 15;
    const int ty = tid >> 4;

    // A (weights) load mapping: 128 rows x 8 k, float4 per thread
    const int arow = tid >> 1;
    const int acol = (tid & 1) * 4;
    // B (x) load mapping: 8 rows x 128 n, float4 per thread
    const int brow = tid >> 5;
    const int bcol = (tid & 31) * 4;

    const int am = m0 + arow;
    const float* wptr = (am < 512) ? (qk_w + (size_t)am * 256 + acol)
                                   : (v_w + (size_t)(am - 512) * 256 + acol);
    const int nb = n0 + bcol;
    const float* xptr = x + (size_t)b * CIN * HW + (size_t)brow * HW + nb;

    float acc[8][8];
#pragma unroll
    for (int i = 0; i < 8; ++i)
#pragma unroll
        for (int j = 0; j < 8; ++j) acc[i][j] = 0.f;

    for (int k0 = 0; k0 < 256; k0 += 8) {
        float4 av = *reinterpret_cast<const float4*>(wptr + k0);
        float4 bv;
        const float* p = xptr + (size_t)k0 * HW;
        if (nb + 3 < HW) {
            bv = *reinterpret_cast<const float4*>(p);
        } else {
            bv.x = (nb + 0 < HW) ? p[0] : 0.f;
            bv.y = (nb + 1 < HW) ? p[1] : 0.f;
            bv.z = (nb + 2 < HW) ? p[2] : 0.f;
            bv.w = (nb + 3 < HW) ? p[3] : 0.f;
        }
        As[acol + 0][arow] = av.x;
        As[acol + 1][arow] = av.y;
        As[acol + 2][arow] = av.z;
        As[acol + 3][arow] = av.w;
        *reinterpret_cast<float4*>(&Bs[brow][bcol]) = bv;
        __syncthreads();

#pragma unroll
        for (int kk = 0; kk < 8; ++kk) {
            float a[8], bb[8];
            *reinterpret_cast<float4*>(a)      = *reinterpret_cast<const float4*>(&As[kk][ty * 8]);
            *reinterpret_cast<float4*>(a + 4)  = *reinterpret_cast<const float4*>(&As[kk][ty * 8 + 4]);
            *reinterpret_cast<float4*>(bb)     = *reinterpret_cast<const float4*>(&Bs[kk][tx * 8]);
            *reinterpret_cast<float4*>(bb + 4) = *reinterpret_cast<const float4*>(&Bs[kk][tx * 8 + 4]);
#pragma unroll
            for (int i = 0; i < 8; ++i)
#pragma unroll
                for (int j = 0; j < 8; ++j)
                    acc[i][j] = fmaf(a[i], bb[j], acc[i][j]);
        }
        __syncthreads();
    }

    const bool isv = (m0 >= 512);   // whole tile is v (m0 in {512,640})
#pragma unroll
    for (int j = 0; j < 8; ++j) {
        const int n = n0 + tx * 8 + j;
        if (n >= HW) continue;
        float* dst = g_buf + ((size_t)b * HW + n) * OCH + (m0 + ty * 8);
        float4 o0, o1;
        o0.x = acc[0][j]; o0.y = acc[1][j]; o0.z = acc[2][j]; o0.w = acc[3][j];
        o1.x = acc[4][j]; o1.y = acc[5][j]; o1.z = acc[6][j]; o1.w = acc[7][j];
        if (isv) {
            o0.x = fmaxf(o0.x, 0.f); o0.y = fmaxf(o0.y, 0.f);
            o0.z = fmaxf(o0.z, 0.f); o0.w = fmaxf(o0.w, 0.f);
            o1.x = fmaxf(o1.x, 0.f); o1.y = fmaxf(o1.y, 0.f);
            o1.z = fmaxf(o1.z, 0.f); o1.w = fmaxf(o1.w, 0.f);
        }
        *reinterpret_cast<float4*>(dst)     = o0;
        *reinterpret_cast<float4*>(dst + 4) = o1;
    }
}

// ---------------------------------------------------------------------------
// Kernel 2: window attention. One block per (window, batch).
// partition 0 = remote (dilated grid, writes out), 1 = close (contiguous, +=)
// All 4 heads processed concurrently. 4x4 register tiling in both GEMM stages.
// ---------------------------------------------------------------------------
__global__ __launch_bounds__(512) void attn_kernel(float* __restrict__ out, int partition)
{
    extern __shared__ float smem[];
    float* s_in = smem;                    // [49][SIN] : 768 channels per pixel
    float* s_S  = smem + NTOK * SIN;       // [4][49*49] logits -> probs

    __shared__ int s_p[NTOK];

    const int b   = blockIdx.z;
    const int win = blockIdx.x;
    const int j1  = win >> 3;
    const int j2  = win & 7;
    const int tid = threadIdx.x;

    if (tid < NTOK) {
        int h1 = tid / 7, w1 = tid - h1 * 7;
        int hh, ww;
        if (partition == 0) { hh = h1 * 8 + j1; ww = w1 * 8 + j2; }   // remote: dilated
        else                { hh = j1 * 7 + h1; ww = j2 * 7 + w1; }   // close: contiguous
        s_p[tid] = hh * WIMG + ww;
    }
    __syncthreads();

    // ---- stage 768 channels x 49 pixels into smem (coalesced 768-float rows) ----
    const float* src_base = g_buf + (size_t)b * HW * OCH;
    for (int pix = 0; pix < NTOK; ++pix) {
        const float* src = src_base + (size_t)s_p[pix] * OCH;
        float* dst = s_in + pix * SIN;
        for (int o = tid; o < OCH; o += 512) dst[o] = src[o];
    }
    __syncthreads();

    // ---- S = (q k^T) * scale, all 4 heads. 13x13 tiles of 4x4 per head ----
    for (int t = tid; t < 4 * 169; t += 512) {
        const int h  = t / 169;
        const int r  = t - h * 169;
        const int rq = r / 13;
        const int ti = rq * 4;
        const int tj = (r - rq * 13) * 4;
        const float* qp[4];
        const float* kp[4];
#pragma unroll
        for (int ii = 0; ii < 4; ++ii) {
            int iq = ti + ii; if (iq > 48) iq = 48;
            int jq = tj + ii; if (jq > 48) jq = 48;
            qp[ii] = s_in + iq * SIN + h * 64;         // q: channels [0,256)
            kp[ii] = s_in + jq * SIN + 256 + h * 64;   // k: channels [256,512)
        }
        float acc[4][4];
#pragma unroll
        for (int ii = 0; ii < 4; ++ii)
#pragma unroll
            for (int jj = 0; jj < 4; ++jj) acc[ii][jj] = 0.f;
#pragma unroll 8
        for (int d = 0; d < 64; ++d) {
            float qv[4], kv[4];
#pragma unroll
            for (int ii = 0; ii < 4; ++ii) { qv[ii] = qp[ii][d]; kv[ii] = kp[ii][d]; }
#pragma unroll
            for (int ii = 0; ii < 4; ++ii)
#pragma unroll
                for (int jj = 0; jj < 4; ++jj)
                    acc[ii][jj] = fmaf(qv[ii], kv[jj], acc[ii][jj]);
        }
        float* Sh = s_S + h * 2401;
#pragma unroll
        for (int ii = 0; ii < 4; ++ii)
#pragma unroll
            for (int jj = 0; jj < 4; ++jj) {
                const int i = ti + ii, j = tj + jj;
                if (i < 49 && j < 49) Sh[i * 49 + j] = acc[ii][jj] * 0.125f;
            }
    }
    __syncthreads();

    // ---- softmax over rows (one warp per row) ----
    const int warp = tid >> 5, lane = tid & 31;
    for (int row = warp; row < 4 * 49; row += 16) {
        const int h = row / 49;
        const int i = row - h * 49;
        float* Srow = s_S + h * 2401 + i * 49;
        float v0 = Srow[lane];
        float v1 = (lane < 17) ? Srow[lane + 32] : -3.0e38f;
        float m = fmaxf(v0, v1);
#pragma unroll
        for (int off = 16; off; off >>= 1) m = fmaxf(m, __shfl_xor_sync(0xffffffffu, m, off));
        float e0 = __expf(v0 - m);
        float e1 = (lane < 17) ? __expf(v1 - m) : 0.f;
        float s = e0 + e1;
#pragma unroll
        for (int off = 16; off; off >>= 1) s += __shfl_xor_sync(0xffffffffu, s, off);
        const float inv = 1.f / s;
        Srow[lane] = e0 * inv;
        if (lane < 17) Srow[lane + 32] = e1 * inv;
    }
    __syncthreads();

    // ---- O = P @ v, all 4 heads. 13x16 tiles of 4(i) x 4(d) per head ----
    for (int t = tid; t < 4 * 208; t += 512) {
        const int h  = t / 208;
        const int r  = t - h * 208;
        const int ti = (r / 16) * 4;
        const int td = (r & 15) * 4;
        const float* Pp[4];
#pragma unroll
        for (int ii = 0; ii < 4; ++ii) {
            int iq = ti + ii; if (iq > 48) iq = 48;
            Pp[ii] = s_S + h * 2401 + iq * 49;
        }
        float acc[4][4];
#pragma unroll
        for (int ii = 0; ii < 4; ++ii)
#pragma unroll
            for (int dd = 0; dd < 4; ++dd) acc[ii][dd] = 0.f;
#pragma unroll 7
        for (int j = 0; j < 49; ++j) {
            float pv[4];
#pragma unroll
            for (int ii = 0; ii < 4; ++ii) pv[ii] = Pp[ii][j];
            const float* vr = s_in + j * SIN + 512 + h * 64 + td;   // v: channels [512,768)
            float vv[4];
#pragma unroll
            for (int dd = 0; dd < 4; ++dd) vv[dd] = vr[dd];
#pragma unroll
            for (int ii = 0; ii < 4; ++ii)
#pragma unroll
                for (int dd = 0; dd < 4; ++dd)
                    acc[ii][dd] = fmaf(pv[ii], vv[dd], acc[ii][dd]);
        }
#pragma unroll
        for (int ii = 0; ii < 4; ++ii) {
            const int i = ti + ii;
            if (i >= 49) continue;
            const int p = s_p[i];
            float* obase = out + ((size_t)b * 256 + h * 64 + td) * HW + p;
            if (partition == 0) {
#pragma unroll
                for (int dd = 0; dd < 4; ++dd) obase[(size_t)dd * HW] = acc[ii][dd];
            } else {
#pragma unroll
                for (int dd = 0; dd < 4; ++dd) obase[(size_t)dd * HW] += acc[ii][dd];
            }
        }
    }
}

// ---------------------------------------------------------------------------
extern "C" void kernel_launch(void* const* d_in, const int* in_sizes, int n_in,
                              void* d_out, int out_size)
{
    const float* x    = (const float*)d_in[0];
    const float* qk_w = (const float*)d_in[1];
    const float* v_w  = (const float*)d_in[2];
    float* out = (float*)d_out;

    conv_kernel<<<dim3(25, 6, 32), 256>>>(x, qk_w, v_w);

    const int smem_bytes = (NTOK * SIN + 4 * 2401) * (int)sizeof(float);  // 189,140 B
    cudaFuncSetAttribute(attn_kernel, cudaFuncAttributeMaxDynamicSharedMemorySize, smem_bytes);
    attn_kernel<<<dim3(64, 1, 32), 512, smem_bytes>>>(out, 0);  // remote: write
    attn_kernel<<<dim3(64, 1, 32), 512, smem_bytes>>>(out, 1);  // close: accumulate
}

// round 3
// speedup vs baseline: 1.5281x; 1.5281x over previous
#include <cuda_runtime.h>
#include <cstdint>
#include <cstddef>

#define BATCH 32
#define CIN   256
#define HW    3136
#define WIMG  56
#define NTOK  49
#define OCH   768

// Scratch: conv output, pixel-major [b][p][o] ; o: 0..511 = qk, 512..767 = v(relu)
__device__ float g_buf[(size_t)BATCH * HW * OCH];

// ---------------------------------------------------------------------------
// Kernel 1: fused 1x1 convs as GEMM  C[768,3136] = W[768,256] @ X[256,3136]
// Double-buffered smem, one sync per k-step.
// ---------------------------------------------------------------------------
__device__ __forceinline__ float4 loadB_guard(const float* p, int nb) {
    if (nb + 3 < HW) return *reinterpret_cast<const float4*>(p);
    float4 v;
    v.x = (nb + 0 < HW) ? p[0] : 0.f;
    v.y = (nb + 1 < HW) ? p[1] : 0.f;
    v.z = (nb + 2 < HW) ? p[2] : 0.f;
    v.w = (nb + 3 < HW) ? p[3] : 0.f;
    return v;
}

__global__ __launch_bounds__(256) void conv_kernel(
    const float* __restrict__ x,
    const float* __restrict__ qk_w,
    const float* __restrict__ v_w)
{
    const int b  = blockIdx.z;
    const int m0 = blockIdx.y * 128;
    const int n0 = blockIdx.x * 128;

    __shared__ float As[2][8][128];
    __shared__ float Bs[2][8][128];

    const int tid = threadIdx.x;
    const int tx = tid & 15;
    const int ty = tid >> 4;

    // A (weights) load mapping: 128 rows x 8 k, float4 per thread
    const int arow = tid >> 1;
    const int acol = (tid & 1) * 4;
    // B (x) load mapping: 8 rows x 128 n, float4 per thread
    const int brow = tid >> 5;
    const int bcol = (tid & 31) * 4;

    const int am = m0 + arow;
    const float* wptr = (am < 512) ? (qk_w + (size_t)am * 256 + acol)
                                   : (v_w + (size_t)(am - 512) * 256 + acol);
    const int nb = n0 + bcol;
    const float* xptr = x + (size_t)b * CIN * HW + (size_t)brow * HW + nb;

    float acc[8][8];
#pragma unroll
    for (int i = 0; i < 8; ++i)
#pragma unroll
        for (int j = 0; j < 8; ++j) acc[i][j] = 0.f;

    // prologue: stage k0 = 0 into buffer 0
    {
        float4 av = *reinterpret_cast<const float4*>(wptr);
        float4 bv = loadB_guard(xptr, nb);
        As[0][acol + 0][arow] = av.x;
        As[0][acol + 1][arow] = av.y;
        As[0][acol + 2][arow] = av.z;
        As[0][acol + 3][arow] = av.w;
        *reinterpret_cast<float4*>(&Bs[0][brow][bcol]) = bv;
    }
    __syncthreads();

    int cur = 0;
    for (int k0 = 0; k0 < 256; k0 += 8) {
        const bool more = (k0 + 8 < 256);
        float4 av_n, bv_n;
        if (more) {
            av_n = *reinterpret_cast<const float4*>(wptr + k0 + 8);
            bv_n = loadB_guard(xptr + (size_t)(k0 + 8) * HW, nb);
        }

#pragma unroll
        for (int kk = 0; kk < 8; ++kk) {
            float a[8], bb[8];
            *reinterpret_cast<float4*>(a)      = *reinterpret_cast<const float4*>(&As[cur][kk][ty * 8]);
            *reinterpret_cast<float4*>(a + 4)  = *reinterpret_cast<const float4*>(&As[cur][kk][ty * 8 + 4]);
            *reinterpret_cast<float4*>(bb)     = *reinterpret_cast<const float4*>(&Bs[cur][kk][tx * 8]);
            *reinterpret_cast<float4*>(bb + 4) = *reinterpret_cast<const float4*>(&Bs[cur][kk][tx * 8 + 4]);
#pragma unroll
            for (int i = 0; i < 8; ++i)
#pragma unroll
                for (int j = 0; j < 8; ++j)
                    acc[i][j] = fmaf(a[i], bb[j], acc[i][j]);
        }

        if (more) {
            const int nxt = cur ^ 1;
            As[nxt][acol + 0][arow] = av_n.x;
            As[nxt][acol + 1][arow] = av_n.y;
            As[nxt][acol + 2][arow] = av_n.z;
            As[nxt][acol + 3][arow] = av_n.w;
            *reinterpret_cast<float4*>(&Bs[nxt][brow][bcol]) = bv_n;
        }
        __syncthreads();
        cur ^= 1;
    }

    const bool isv = (m0 >= 512);   // whole tile is v (m0 in {512,640})
#pragma unroll
    for (int j = 0; j < 8; ++j) {
        const int n = n0 + tx * 8 + j;
        if (n >= HW) continue;
        float* dst = g_buf + ((size_t)b * HW + n) * OCH + (m0 + ty * 8);
        float4 o0, o1;
        o0.x = acc[0][j]; o0.y = acc[1][j]; o0.z = acc[2][j]; o0.w = acc[3][j];
        o1.x = acc[4][j]; o1.y = acc[5][j]; o1.z = acc[6][j]; o1.w = acc[7][j];
        if (isv) {
            o0.x = fmaxf(o0.x, 0.f); o0.y = fmaxf(o0.y, 0.f);
            o0.z = fmaxf(o0.z, 0.f); o0.w = fmaxf(o0.w, 0.f);
            o1.x = fmaxf(o1.x, 0.f); o1.y = fmaxf(o1.y, 0.f);
            o1.z = fmaxf(o1.z, 0.f); o1.w = fmaxf(o1.w, 0.f);
        }
        *reinterpret_cast<float4*>(dst)     = o0;
        *reinterpret_cast<float4*>(dst + 4) = o1;
    }
}

// ---------------------------------------------------------------------------
// Kernel 2: window attention, one block per (window, batch, head).
// partition 0 = remote (dilated grid, writes out), 1 = close (contiguous, +=)
// smem = 48KB -> 4 CTAs/SM. 4x4 register tiling in both GEMM stages.
// ---------------------------------------------------------------------------
#define SQ 65   // q/k/v row stride
#define SS 50   // S row stride

__global__ __launch_bounds__(256) void attn_kernel(float* __restrict__ out, int partition)
{
    __shared__ float s_q[NTOK * SQ];
    __shared__ float s_k[NTOK * SQ];
    __shared__ float s_v[NTOK * SQ];
    __shared__ float s_S[NTOK * SS];
    __shared__ int   s_p[NTOK];

    const int b   = blockIdx.z;
    const int h   = blockIdx.y;
    const int win = blockIdx.x;
    const int j1  = win >> 3;
    const int j2  = win & 7;
    const int tid = threadIdx.x;

    if (tid < NTOK) {
        int h1 = tid / 7, w1 = tid - h1 * 7;
        int hh, ww;
        if (partition == 0) { hh = h1 * 8 + j1; ww = w1 * 8 + j2; }   // remote: dilated
        else                { hh = j1 * 7 + h1; ww = j2 * 7 + w1; }   // close: contiguous
        s_p[tid] = hh * WIMG + ww;
    }
    __syncthreads();

    // ---- stage q,k,v head slices: 49 pixels x 3 x 64 floats, float4 gmem reads ----
    const float* base = g_buf + (size_t)b * HW * OCH + h * 64;
    for (int idx = tid; idx < NTOK * 48; idx += 256) {
        const int pix = idx / 48;
        const int r   = idx - pix * 48;
        const int seg = r >> 4;         // 0=q,1=k,2=v
        const int d4  = r & 15;
        const float4 val = *reinterpret_cast<const float4*>(
            base + (size_t)s_p[pix] * OCH + seg * 256 + d4 * 4);
        float* dst = (seg == 0 ? s_q : seg == 1 ? s_k : s_v) + pix * SQ + d4 * 4;
        dst[0] = val.x; dst[1] = val.y; dst[2] = val.z; dst[3] = val.w;
    }
    __syncthreads();

    // ---- S = (q k^T) * scale : 13x13 grid of 4x4 tiles ----
    if (tid < 169) {
        const int ti = (tid / 13) * 4;
        const int tj = (tid % 13) * 4;
        const float* qp[4];
        const float* kp[4];
#pragma unroll
        for (int ii = 0; ii < 4; ++ii) {
            int iq = ti + ii; if (iq > 48) iq = 48;
            int jq = tj + ii; if (jq > 48) jq = 48;
            qp[ii] = s_q + iq * SQ;
            kp[ii] = s_k + jq * SQ;
        }
        float acc[4][4];
#pragma unroll
        for (int ii = 0; ii < 4; ++ii)
#pragma unroll
            for (int jj = 0; jj < 4; ++jj) acc[ii][jj] = 0.f;
#pragma unroll 8
        for (int d = 0; d < 64; ++d) {
            float qv[4], kv[4];
#pragma unroll
            for (int ii = 0; ii < 4; ++ii) { qv[ii] = qp[ii][d]; kv[ii] = kp[ii][d]; }
#pragma unroll
            for (int ii = 0; ii < 4; ++ii)
#pragma unroll
                for (int jj = 0; jj < 4; ++jj)
                    acc[ii][jj] = fmaf(qv[ii], kv[jj], acc[ii][jj]);
        }
#pragma unroll
        for (int ii = 0; ii < 4; ++ii)
#pragma unroll
            for (int jj = 0; jj < 4; ++jj) {
                const int i = ti + ii, j = tj + jj;
                if (i < NTOK && j < NTOK) s_S[i * SS + j] = acc[ii][jj] * 0.125f;
            }
    }
    __syncthreads();

    // ---- softmax over rows (one warp per row) ----
    const int warp = tid >> 5, lane = tid & 31;
    for (int row = warp; row < NTOK; row += 8) {
        float* Srow = s_S + row * SS;
        float v0 = Srow[lane];
        float v1 = (lane < 17) ? Srow[lane + 32] : -3.0e38f;
        float m = fmaxf(v0, v1);
#pragma unroll
        for (int off = 16; off; off >>= 1) m = fmaxf(m, __shfl_xor_sync(0xffffffffu, m, off));
        float e0 = __expf(v0 - m);
        float e1 = (lane < 17) ? __expf(v1 - m) : 0.f;
        float s = e0 + e1;
#pragma unroll
        for (int off = 16; off; off >>= 1) s += __shfl_xor_sync(0xffffffffu, s, off);
        const float inv = 1.f / s;
        Srow[lane] = e0 * inv;
        if (lane < 17) Srow[lane + 32] = e1 * inv;
    }
    __syncthreads();

    // ---- O = P @ v : 13(i) x 16(d) grid of 4x4 tiles ----
    if (tid < 208) {
        const int ti = (tid / 16) * 4;
        const int td = (tid & 15) * 4;
        const float* Pp[4];
#pragma unroll
        for (int ii = 0; ii < 4; ++ii) {
            int iq = ti + ii; if (iq > 48) iq = 48;
            Pp[ii] = s_S + iq * SS;
        }
        float acc[4][4];
#pragma unroll
        for (int ii = 0; ii < 4; ++ii)
#pragma unroll
            for (int dd = 0; dd < 4; ++dd) acc[ii][dd] = 0.f;
#pragma unroll 7
        for (int j = 0; j < NTOK; ++j) {
            float pv[4];
#pragma unroll
            for (int ii = 0; ii < 4; ++ii) pv[ii] = Pp[ii][j];
            const float* vr = s_v + j * SQ + td;
            float vv[4];
#pragma unroll
            for (int dd = 0; dd < 4; ++dd) vv[dd] = vr[dd];
#pragma unroll
            for (int ii = 0; ii < 4; ++ii)
#pragma unroll
                for (int dd = 0; dd < 4; ++dd)
                    acc[ii][dd] = fmaf(pv[ii], vv[dd], acc[ii][dd]);
        }
#pragma unroll
        for (int ii = 0; ii < 4; ++ii) {
            const int i = ti + ii;
            if (i >= NTOK) continue;
            const int p = s_p[i];
            float* obase = out + ((size_t)b * 256 + h * 64 + td) * HW + p;
            if (partition == 0) {
#pragma unroll
                for (int dd = 0; dd < 4; ++dd) obase[(size_t)dd * HW] = acc[ii][dd];
            } else {
#pragma unroll
                for (int dd = 0; dd < 4; ++dd) obase[(size_t)dd * HW] += acc[ii][dd];
            }
        }
    }
}

// ---------------------------------------------------------------------------
extern "C" void kernel_launch(void* const* d_in, const int* in_sizes, int n_in,
                              void* d_out, int out_size)
{
    const float* x    = (const float*)d_in[0];
    const float* qk_w = (const float*)d_in[1];
    const float* v_w  = (const float*)d_in[2];
    float* out = (float*)d_out;

    conv_kernel<<<dim3(25, 6, 32), 256>>>(x, qk_w, v_w);

    attn_kernel<<<dim3(64, 4, 32), 256>>>(out, 0);  // remote: write
    attn_kernel<<<dim3(64, 4, 32), 256>>>(out, 1);  // close: accumulate
}

// round 4
// speedup vs baseline: 1.9937x; 1.3047x over previous
#include <cuda_runtime.h>
#include <cstdint>
#include <cstddef>

#define BATCH 32
#define CIN   256
#define HW    3136
#define WIMG  56
#define NTOK  49
#define OCH   768

// Scratch: conv output, pixel-major [b][p][o] ; o: 0..511 = qk, 512..767 = v(relu)
__device__ float g_buf[(size_t)BATCH * HW * OCH];

// ---------------------------------------------------------------------------
// Kernel 1: fused 1x1 convs as tf32 tensor-core GEMM
//   C[768,3136] = W[768,256] @ X[256,3136]  per batch
// Block tile 128(m) x 128(n), K chunks of 32, double-buffered smem.
// 8 warps, each computes 64x32 via 4x4 grid of m16n8k8 mma.sync.
// smem layouts As[k][m], Bs[k][n] with stride 136 (conflict-free frag loads).
// ---------------------------------------------------------------------------
#define KC     32          // k per chunk
#define SPAD   136         // smem row stride (136 % 32 == 8 -> 8*tig+g conflict-free)
#define ABUF   (KC * SPAD) // uints per buffer

__device__ __forceinline__ uint32_t f2tf32(float f) {
    uint32_t u;
    asm("cvt.rna.tf32.f32 %0, %1;" : "=r"(u) : "f"(f));
    return u;
}

__device__ __forceinline__ void mma_tf32(float* c, const uint32_t* a, const uint32_t* b) {
    asm volatile(
        "mma.sync.aligned.m16n8k8.row.col.f32.tf32.tf32.f32 "
        "{%0,%1,%2,%3}, {%4,%5,%6,%7}, {%8,%9}, {%0,%1,%2,%3};"
        : "+f"(c[0]), "+f"(c[1]), "+f"(c[2]), "+f"(c[3])
        : "r"(a[0]), "r"(a[1]), "r"(a[2]), "r"(a[3]), "r"(b[0]), "r"(b[1]));
}

__global__ __launch_bounds__(256, 2) void conv_kernel(
    const float* __restrict__ x,
    const float* __restrict__ qk_w,
    const float* __restrict__ v_w)
{
    extern __shared__ uint32_t smem[];
    uint32_t* As = smem;               // [2][KC][SPAD]
    uint32_t* Bs = smem + 2 * ABUF;    // [2][KC][SPAD]

    const int b  = blockIdx.z;
    const int m0 = blockIdx.y * 128;
    const int n0 = blockIdx.x * 128;

    const int tid  = threadIdx.x;
    const int lane = tid & 31;
    const int wid  = tid >> 5;
    const int g    = lane >> 2;     // group 0..7
    const int tig  = lane & 3;      // thread-in-group
    const int wm   = (wid >> 2) * 64;   // warp m offset within tile
    const int wn   = (wid & 3) * 32;    // warp n offset

    // ---- global load mappings ----
    // A: W[768,256] row-major. thread: m row = mA, k = kq*16 + {0,4,8,12}
    const int mA = tid & 127;
    const int kq = tid >> 7;                // 0 or 1
    const int am = m0 + mA;
    const float* wptr = (am < 512) ? (qk_w + (size_t)am * 256)
                                   : (v_w + (size_t)(am - 512) * 256);
    // B: X[256,3136]. thread: n = n0 + (lane)*4, k rows kr + 8j
    const int nIdx = (tid & 31) * 4;
    const int kr   = tid >> 5;              // 0..7
    const int nB   = n0 + nIdx;
    const float* xptr = x + (size_t)b * CIN * HW + nB;
    const bool nOK = (nB < HW);             // HW % 4 == 0, so float4 all-or-nothing

    float acc[4][4][4];
#pragma unroll
    for (int mm = 0; mm < 4; ++mm)
#pragma unroll
        for (int nn = 0; nn < 4; ++nn)
#pragma unroll
            for (int r = 0; r < 4; ++r) acc[mm][nn][r] = 0.f;

    float4 avr[4], bvr[4];
    auto load_chunk = [&](int k0) {
#pragma unroll
        for (int q = 0; q < 4; ++q)
            avr[q] = *reinterpret_cast<const float4*>(wptr + k0 + kq * 16 + q * 4);
#pragma unroll
        for (int j = 0; j < 4; ++j) {
            if (nOK) bvr[j] = *reinterpret_cast<const float4*>(xptr + (size_t)(k0 + kr + 8 * j) * HW);
            else     bvr[j] = make_float4(0.f, 0.f, 0.f, 0.f);
        }
    };
    auto store_chunk = [&](int buf) {
        uint32_t* Ab = As + buf * ABUF;
        uint32_t* Bb = Bs + buf * ABUF;
#pragma unroll
        for (int q = 0; q < 4; ++q) {
            const int kk = kq * 16 + q * 4;
            Ab[(kk + 0) * SPAD + mA] = f2tf32(avr[q].x);
            Ab[(kk + 1) * SPAD + mA] = f2tf32(avr[q].y);
            Ab[(kk + 2) * SPAD + mA] = f2tf32(avr[q].z);
            Ab[(kk + 3) * SPAD + mA] = f2tf32(avr[q].w);
        }
#pragma unroll
        for (int j = 0; j < 4; ++j) {
            uint32_t* d = Bb + (kr + 8 * j) * SPAD + nIdx;
            d[0] = f2tf32(bvr[j].x);
            d[1] = f2tf32(bvr[j].y);
            d[2] = f2tf32(bvr[j].z);
            d[3] = f2tf32(bvr[j].w);
        }
    };

    // prologue
    load_chunk(0);
    store_chunk(0);
    __syncthreads();

    int cur = 0;
    for (int k0 = 0; k0 < 256; k0 += KC) {
        const bool more = (k0 + KC < 256);
        if (more) load_chunk(k0 + KC);

        const uint32_t* Ab = As + cur * ABUF;
        const uint32_t* Bb = Bs + cur * ABUF;
#pragma unroll
        for (int kc = 0; kc < 4; ++kc) {
            const int k8 = kc * 8;
            uint32_t a[4][4], bb[4][2];
#pragma unroll
            for (int mm = 0; mm < 4; ++mm) {
                const int row = wm + mm * 16 + g;
                a[mm][0] = Ab[(k8 + tig) * SPAD + row];
                a[mm][1] = Ab[(k8 + tig) * SPAD + row + 8];
                a[mm][2] = Ab[(k8 + tig + 4) * SPAD + row];
                a[mm][3] = Ab[(k8 + tig + 4) * SPAD + row + 8];
            }
#pragma unroll
            for (int nn = 0; nn < 4; ++nn) {
                const int col = wn + nn * 8 + g;
                bb[nn][0] = Bb[(k8 + tig) * SPAD + col];
                bb[nn][1] = Bb[(k8 + tig + 4) * SPAD + col];
            }
#pragma unroll
            for (int mm = 0; mm < 4; ++mm)
#pragma unroll
                for (int nn = 0; nn < 4; ++nn)
                    mma_tf32(acc[mm][nn], a[mm], bb[nn]);
        }

        if (more) {
            store_chunk(cur ^ 1);
        }
        __syncthreads();
        cur ^= 1;
    }

    // ---- epilogue: scatter to g_buf pixel-major ----
    const bool isv = (m0 >= 512);
    const float* dummy = nullptr; (void)dummy;
#pragma unroll
    for (int mm = 0; mm < 4; ++mm) {
#pragma unroll
        for (int nn = 0; nn < 4; ++nn) {
            const int ncol = n0 + wn + nn * 8 + 2 * tig;
            const int mrow = m0 + wm + mm * 16 + g;
            float v0 = acc[mm][nn][0];
            float v1 = acc[mm][nn][1];
            float v2 = acc[mm][nn][2];
            float v3 = acc[mm][nn][3];
            if (isv) {
                v0 = fmaxf(v0, 0.f); v1 = fmaxf(v1, 0.f);
                v2 = fmaxf(v2, 0.f); v3 = fmaxf(v3, 0.f);
            }
            if (ncol < HW) {
                float* d0 = g_buf + ((size_t)b * HW + ncol) * OCH + mrow;
                d0[0] = v0;          // (mrow,   ncol)
                d0[8] = v2;          // (mrow+8, ncol)
            }
            if (ncol + 1 < HW) {
                float* d1 = g_buf + ((size_t)b * HW + ncol + 1) * OCH + mrow;
                d1[0] = v1;          // (mrow,   ncol+1)
                d1[8] = v3;          // (mrow+8, ncol+1)
            }
        }
    }
}

// ---------------------------------------------------------------------------
// Kernel 2: window attention, one block per (window, batch, head).
// partition 0 = remote (dilated grid, writes out), 1 = close (contiguous, +=)
// smem = 48KB -> 4 CTAs/SM. 4x4 register tiling in both GEMM stages.
// ---------------------------------------------------------------------------
#define SQ 65   // q/k/v row stride
#define SS 50   // S row stride

__global__ __launch_bounds__(256) void attn_kernel(float* __restrict__ out, int partition)
{
    __shared__ float s_q[NTOK * SQ];
    __shared__ float s_k[NTOK * SQ];
    __shared__ float s_v[NTOK * SQ];
    __shared__ float s_S[NTOK * SS];
    __shared__ int   s_p[NTOK];

    const int b   = blockIdx.z;
    const int h   = blockIdx.y;
    const int win = blockIdx.x;
    const int j1  = win >> 3;
    const int j2  = win & 7;
    const int tid = threadIdx.x;

    if (tid < NTOK) {
        int h1 = tid / 7, w1 = tid - h1 * 7;
        int hh, ww;
        if (partition == 0) { hh = h1 * 8 + j1; ww = w1 * 8 + j2; }   // remote: dilated
        else                { hh = j1 * 7 + h1; ww = j2 * 7 + w1; }   // close: contiguous
        s_p[tid] = hh * WIMG + ww;
    }
    __syncthreads();

    // ---- stage q,k,v head slices: 49 pixels x 3 x 64 floats, float4 gmem reads ----
    const float* base = g_buf + (size_t)b * HW * OCH + h * 64;
    for (int idx = tid; idx < NTOK * 48; idx += 256) {
        const int pix = idx / 48;
        const int r   = idx - pix * 48;
        const int seg = r >> 4;         // 0=q,1=k,2=v
        const int d4  = r & 15;
        const float4 val = *reinterpret_cast<const float4*>(
            base + (size_t)s_p[pix] * OCH + seg * 256 + d4 * 4);
        float* dst = (seg == 0 ? s_q : seg == 1 ? s_k : s_v) + pix * SQ + d4 * 4;
        dst[0] = val.x; dst[1] = val.y; dst[2] = val.z; dst[3] = val.w;
    }
    __syncthreads();

    // ---- S = (q k^T) * scale : 13x13 grid of 4x4 tiles ----
    if (tid < 169) {
        const int ti = (tid / 13) * 4;
        const int tj = (tid % 13) * 4;
        const float* qp[4];
        const float* kp[4];
#pragma unroll
        for (int ii = 0; ii < 4; ++ii) {
            int iq = ti + ii; if (iq > 48) iq = 48;
            int jq = tj + ii; if (jq > 48) jq = 48;
            qp[ii] = s_q + iq * SQ;
            kp[ii] = s_k + jq * SQ;
        }
        float acc[4][4];
#pragma unroll
        for (int ii = 0; ii < 4; ++ii)
#pragma unroll
            for (int jj = 0; jj < 4; ++jj) acc[ii][jj] = 0.f;
#pragma unroll 8
        for (int d = 0; d < 64; ++d) {
            float qv[4], kv[4];
#pragma unroll
            for (int ii = 0; ii < 4; ++ii) { qv[ii] = qp[ii][d]; kv[ii] = kp[ii][d]; }
#pragma unroll
            for (int ii = 0; ii < 4; ++ii)
#pragma unroll
                for (int jj = 0; jj < 4; ++jj)
                    acc[ii][jj] = fmaf(qv[ii], kv[jj], acc[ii][jj]);
        }
#pragma unroll
        for (int ii = 0; ii < 4; ++ii)
#pragma unroll
            for (int jj = 0; jj < 4; ++jj) {
                const int i = ti + ii, j = tj + jj;
                if (i < NTOK && j < NTOK) s_S[i * SS + j] = acc[ii][jj] * 0.125f;
            }
    }
    __syncthreads();

    // ---- softmax over rows (one warp per row) ----
    const int warp = tid >> 5, lane = tid & 31;
    for (int row = warp; row < NTOK; row += 8) {
        float* Srow = s_S + row * SS;
        float v0 = Srow[lane];
        float v1 = (lane < 17) ? Srow[lane + 32] : -3.0e38f;
        float m = fmaxf(v0, v1);
#pragma unroll
        for (int off = 16; off; off >>= 1) m = fmaxf(m, __shfl_xor_sync(0xffffffffu, m, off));
        float e0 = __expf(v0 - m);
        float e1 = (lane < 17) ? __expf(v1 - m) : 0.f;
        float s = e0 + e1;
#pragma unroll
        for (int off = 16; off; off >>= 1) s += __shfl_xor_sync(0xffffffffu, s, off);
        const float inv = 1.f / s;
        Srow[lane] = e0 * inv;
        if (lane < 17) Srow[lane + 32] = e1 * inv;
    }
    __syncthreads();

    // ---- O = P @ v : 13(i) x 16(d) grid of 4x4 tiles ----
    if (tid < 208) {
        const int ti = (tid / 16) * 4;
        const int td = (tid & 15) * 4;
        const float* Pp[4];
#pragma unroll
        for (int ii = 0; ii < 4; ++ii) {
            int iq = ti + ii; if (iq > 48) iq = 48;
            Pp[ii] = s_S + iq * SS;
        }
        float acc[4][4];
#pragma unroll
        for (int ii = 0; ii < 4; ++ii)
#pragma unroll
            for (int dd = 0; dd < 4; ++dd) acc[ii][dd] = 0.f;
#pragma unroll 7
        for (int j = 0; j < NTOK; ++j) {
            float pv[4];
#pragma unroll
            for (int ii = 0; ii < 4; ++ii) pv[ii] = Pp[ii][j];
            const float* vr = s_v + j * SQ + td;
            float vv[4];
#pragma unroll
            for (int dd = 0; dd < 4; ++dd) vv[dd] = vr[dd];
#pragma unroll
            for (int ii = 0; ii < 4; ++ii)
#pragma unroll
                for (int dd = 0; dd < 4; ++dd)
                    acc[ii][dd] = fmaf(pv[ii], vv[dd], acc[ii][dd]);
        }
#pragma unroll
        for (int ii = 0; ii < 4; ++ii) {
            const int i = ti + ii;
            if (i >= NTOK) continue;
            const int p = s_p[i];
            float* obase = out + ((size_t)b * 256 + h * 64 + td) * HW + p;
            if (partition == 0) {
#pragma unroll
                for (int dd = 0; dd < 4; ++dd) obase[(size_t)dd * HW] = acc[ii][dd];
            } else {
#pragma unroll
                for (int dd = 0; dd < 4; ++dd) obase[(size_t)dd * HW] += acc[ii][dd];
            }
        }
    }
}

// ---------------------------------------------------------------------------
extern "C" void kernel_launch(void* const* d_in, const int* in_sizes, int n_in,
                              void* d_out, int out_size)
{
    const float* x    = (const float*)d_in[0];
    const float* qk_w = (const float*)d_in[1];
    const float* v_w  = (const float*)d_in[2];
    float* out = (float*)d_out;

    const int conv_smem = 4 * ABUF * (int)sizeof(uint32_t);   // 69632 B
    cudaFuncSetAttribute(conv_kernel, cudaFuncAttributeMaxDynamicSharedMemorySize, conv_smem);
    conv_kernel<<<dim3(25, 6, 32), 256, conv_smem>>>(x, qk_w, v_w);

    attn_kernel<<<dim3(64, 4, 32), 256>>>(out, 0);  // remote: write
    attn_kernel<<<dim3(64, 4, 32), 256>>>(out, 1);  // close: accumulate
}

// round 6
// speedup vs baseline: 2.4102x; 1.2089x over previous
#include <cuda_runtime.h>
#include <cstdint>
#include <cstddef>

#define BATCH 32
#define CIN   256
#define HW    3136
#define WIMG  56
#define NTOK  49
#define OCH   768

// Scratch: conv output, pixel-major [b][p][o] ; o: 0..511 = qk, 512..767 = v(relu)
__device__ float g_buf[(size_t)BATCH * HW * OCH];

__device__ __forceinline__ uint32_t f2tf32(float f) {
    uint32_t u;
    asm("cvt.rna.tf32.f32 %0, %1;" : "=r"(u) : "f"(f));
    return u;
}

__device__ __forceinline__ void mma_tf32(float* c, const uint32_t* a, const uint32_t* b) {
    asm volatile(
        "mma.sync.aligned.m16n8k8.row.col.f32.tf32.tf32.f32 "
        "{%0,%1,%2,%3}, {%4,%5,%6,%7}, {%8,%9}, {%0,%1,%2,%3};"
        : "+f"(c[0]), "+f"(c[1]), "+f"(c[2]), "+f"(c[3])
        : "r"(a[0]), "r"(a[1]), "r"(a[2]), "r"(a[3]), "r"(b[0]), "r"(b[1]));
}

// ---------------------------------------------------------------------------
// Kernel 1: fused 1x1 convs as tf32 tensor-core GEMM (unchanged from R3)
// ---------------------------------------------------------------------------
#define KC     32
#define SPAD   136
#define ABUF   (KC * SPAD)

__global__ __launch_bounds__(256, 2) void conv_kernel(
    const float* __restrict__ x,
    const float* __restrict__ qk_w,
    const float* __restrict__ v_w)
{
    extern __shared__ uint32_t smem[];
    uint32_t* As = smem;
    uint32_t* Bs = smem + 2 * ABUF;

    const int b  = blockIdx.z;
    const int m0 = blockIdx.y * 128;
    const int n0 = blockIdx.x * 128;

    const int tid  = threadIdx.x;
    const int lane = tid & 31;
    const int wid  = tid >> 5;
    const int g    = lane >> 2;
    const int tig  = lane & 3;
    const int wm   = (wid >> 2) * 64;
    const int wn   = (wid & 3) * 32;

    const int mA = tid & 127;
    const int kq = tid >> 7;
    const int am = m0 + mA;
    const float* wptr = (am < 512) ? (qk_w + (size_t)am * 256)
                                   : (v_w + (size_t)(am - 512) * 256);
    const int nIdx = (tid & 31) * 4;
    const int kr   = tid >> 5;
    const int nB   = n0 + nIdx;
    const float* xptr = x + (size_t)b * CIN * HW + nB;
    const bool nOK = (nB < HW);

    float acc[4][4][4];
#pragma unroll
    for (int mm = 0; mm < 4; ++mm)
#pragma unroll
        for (int nn = 0; nn < 4; ++nn)
#pragma unroll
            for (int r = 0; r < 4; ++r) acc[mm][nn][r] = 0.f;

    float4 avr[4], bvr[4];
    auto load_chunk = [&](int k0) {
#pragma unroll
        for (int q = 0; q < 4; ++q)
            avr[q] = *reinterpret_cast<const float4*>(wptr + k0 + kq * 16 + q * 4);
#pragma unroll
        for (int j = 0; j < 4; ++j) {
            if (nOK) bvr[j] = *reinterpret_cast<const float4*>(xptr + (size_t)(k0 + kr + 8 * j) * HW);
            else     bvr[j] = make_float4(0.f, 0.f, 0.f, 0.f);
        }
    };
    auto store_chunk = [&](int buf) {
        uint32_t* Ab = As + buf * ABUF;
        uint32_t* Bb = Bs + buf * ABUF;
#pragma unroll
        for (int q = 0; q < 4; ++q) {
            const int kk = kq * 16 + q * 4;
            Ab[(kk + 0) * SPAD + mA] = f2tf32(avr[q].x);
            Ab[(kk + 1) * SPAD + mA] = f2tf32(avr[q].y);
            Ab[(kk + 2) * SPAD + mA] = f2tf32(avr[q].z);
            Ab[(kk + 3) * SPAD + mA] = f2tf32(avr[q].w);
        }
#pragma unroll
        for (int j = 0; j < 4; ++j) {
            uint32_t* d = Bb + (kr + 8 * j) * SPAD + nIdx;
            d[0] = f2tf32(bvr[j].x);
            d[1] = f2tf32(bvr[j].y);
            d[2] = f2tf32(bvr[j].z);
            d[3] = f2tf32(bvr[j].w);
        }
    };

    load_chunk(0);
    store_chunk(0);
    __syncthreads();

    int cur = 0;
    for (int k0 = 0; k0 < 256; k0 += KC) {
        const bool more = (k0 + KC < 256);
        if (more) load_chunk(k0 + KC);

        const uint32_t* Ab = As + cur * ABUF;
        const uint32_t* Bb = Bs + cur * ABUF;
#pragma unroll
        for (int kc = 0; kc < 4; ++kc) {
            const int k8 = kc * 8;
            uint32_t a[4][4], bb[4][2];
#pragma unroll
            for (int mm = 0; mm < 4; ++mm) {
                const int row = wm + mm * 16 + g;
                a[mm][0] = Ab[(k8 + tig) * SPAD + row];
                a[mm][1] = Ab[(k8 + tig) * SPAD + row + 8];
                a[mm][2] = Ab[(k8 + tig + 4) * SPAD + row];
                a[mm][3] = Ab[(k8 + tig + 4) * SPAD + row + 8];
            }
#pragma unroll
            for (int nn = 0; nn < 4; ++nn) {
                const int col = wn + nn * 8 + g;
                bb[nn][0] = Bb[(k8 + tig) * SPAD + col];
                bb[nn][1] = Bb[(k8 + tig + 4) * SPAD + col];
            }
#pragma unroll
            for (int mm = 0; mm < 4; ++mm)
#pragma unroll
                for (int nn = 0; nn < 4; ++nn)
                    mma_tf32(acc[mm][nn], a[mm], bb[nn]);
        }

        if (more) store_chunk(cur ^ 1);
        __syncthreads();
        cur ^= 1;
    }

    const bool isv = (m0 >= 512);
#pragma unroll
    for (int mm = 0; mm < 4; ++mm) {
#pragma unroll
        for (int nn = 0; nn < 4; ++nn) {
            const int ncol = n0 + wn + nn * 8 + 2 * tig;
            const int mrow = m0 + wm + mm * 16 + g;
            float v0 = acc[mm][nn][0];
            float v1 = acc[mm][nn][1];
            float v2 = acc[mm][nn][2];
            float v3 = acc[mm][nn][3];
            if (isv) {
                v0 = fmaxf(v0, 0.f); v1 = fmaxf(v1, 0.f);
                v2 = fmaxf(v2, 0.f); v3 = fmaxf(v3, 0.f);
            }
            if (ncol < HW) {
                float* d0 = g_buf + ((size_t)b * HW + ncol) * OCH + mrow;
                d0[0] = v0;
                d0[8] = v2;
            }
            if (ncol + 1 < HW) {
                float* d1 = g_buf + ((size_t)b * HW + ncol + 1) * OCH + mrow;
                d1[0] = v1;
                d1[8] = v3;
            }
        }
    }
}

// ---------------------------------------------------------------------------
// Kernel 2: tf32 tensor-core window attention.
// Block = (win, b, h), 128 threads = 4 warps, each warp one m16 row-tile.
// Padded problem: M=64, N(tokens)=56, D=64. q/k stride 68, v stride 72,
// S stride 60 — all fragment access patterns bank-conflict-free.
// Natural row-major K and V serve directly as mma B operands (B[k][n]=K[n][k]).
// ---------------------------------------------------------------------------
#define QS 68
#define VS 72
#define SST 60

// float offsets inside dynamic smem
#define OFF_Q 0
#define OFF_K (OFF_Q + 64 * QS)            // 4352
#define OFF_V (OFF_K + 56 * QS)            // 8160
#define OFF_S (OFF_V + 56 * VS)            // 12192
#define OFF_P (OFF_S + 64 * SST)           // 16032 (ints)
#define ATTN_SMEM_BYTES ((OFF_P + NTOK) * 4 + 12)

__global__ __launch_bounds__(128) void attn_kernel(float* __restrict__ out, int partition)
{
    extern __shared__ float sm[];
    float* s_q = sm + OFF_Q;
    float* s_k = sm + OFF_K;
    float* s_v = sm + OFF_V;
    float* s_S = sm + OFF_S;
    int*   s_p = reinterpret_cast<int*>(sm + OFF_P);

    const int b   = blockIdx.z;
    const int h   = blockIdx.y;
    const int win = blockIdx.x;
    const int j1  = win >> 3;
    const int j2  = win & 7;
    const int tid  = threadIdx.x;
    const int lane = tid & 31;
    const int wid  = tid >> 5;
    const int g    = lane >> 2;
    const int tig  = lane & 3;
    const int wr   = wid * 16;

    if (tid < NTOK) {
        int h1 = tid / 7, w1 = tid - h1 * 7;
        int hh, ww;
        if (partition == 0) { hh = h1 * 8 + j1; ww = w1 * 8 + j2; }   // remote
        else                { hh = j1 * 7 + h1; ww = j2 * 7 + w1; }   // close
        s_p[tid] = hh * WIMG + ww;
    }
    // zero pad rows (so padded mma lanes stay finite / exact zero)
    for (int i = tid; i < 15 * QS; i += 128) s_q[49 * QS + i] = 0.f;
    for (int i = tid; i < 7 * QS; i += 128)  s_k[49 * QS + i] = 0.f;
    for (int i = tid; i < 7 * VS; i += 128)  s_v[49 * VS + i] = 0.f;
    __syncthreads();

    // ---- stage q,k,v (tf32-converted), fully coalesced float4 reads ----
    const float* base = g_buf + (size_t)b * HW * OCH + h * 64;
    for (int idx = tid; idx < NTOK * 48; idx += 128) {
        const int pix = idx / 48;
        const int r   = idx - pix * 48;
        const int seg = r >> 4;          // 0=q,1=k,2=v
        const int d4  = r & 15;
        const float4 val = *reinterpret_cast<const float4*>(
            base + (size_t)s_p[pix] * OCH + seg * 256 + d4 * 4);
        uint4 t;
        t.x = f2tf32(val.x); t.y = f2tf32(val.y);
        t.z = f2tf32(val.z); t.w = f2tf32(val.w);
        if (seg == 0)      *reinterpret_cast<uint4*>(&s_q[pix * QS + d4 * 4]) = t;
        else if (seg == 1) *reinterpret_cast<uint4*>(&s_k[pix * QS + d4 * 4]) = t;
        else               *reinterpret_cast<uint4*>(&s_v[pix * VS + d4 * 4]) = t;
    }
    __syncthreads();

    // ---- S = Q K^T * scale : per warp 1 m-tile x 7 n-tiles x 8 k-steps ----
    {
        const uint32_t* q32 = reinterpret_cast<const uint32_t*>(s_q);
        const uint32_t* k32 = reinterpret_cast<const uint32_t*>(s_k);
        float cS[7][4];
#pragma unroll
        for (int nt = 0; nt < 7; ++nt)
#pragma unroll
            for (int r = 0; r < 4; ++r) cS[nt][r] = 0.f;

#pragma unroll
        for (int k8 = 0; k8 < 8; ++k8) {
            const int k = k8 * 8;
            uint32_t a[4];
            a[0] = q32[(wr + g) * QS + k + tig];
            a[1] = q32[(wr + g + 8) * QS + k + tig];
            a[2] = q32[(wr + g) * QS + k + tig + 4];
            a[3] = q32[(wr + g + 8) * QS + k + tig + 4];
#pragma unroll
            for (int nt = 0; nt < 7; ++nt) {
                uint32_t bf[2];
                bf[0] = k32[(nt * 8 + g) * QS + k + tig];
                bf[1] = k32[(nt * 8 + g) * QS + k + tig + 4];
                mma_tf32(cS[nt], a, bf);
            }
        }
#pragma unroll
        for (int nt = 0; nt < 7; ++nt) {
            float* S0 = s_S + (wr + g) * SST + nt * 8 + 2 * tig;
            float* S1 = s_S + (wr + g + 8) * SST + nt * 8 + 2 * tig;
            S0[0] = cS[nt][0] * 0.125f;
            S0[1] = cS[nt][1] * 0.125f;
            S1[0] = cS[nt][2] * 0.125f;
            S1[1] = cS[nt][3] * 0.125f;
        }
    }
    __syncthreads();

    // ---- softmax rows 0..48; write probs as tf32 bits; zero pad cols ----
    for (int row = wid; row < NTOK; row += 4) {
        float* Srow = s_S + row * SST;
        float v0 = Srow[lane];
        float v1 = (lane < 17) ? Srow[lane + 32] : -3.0e38f;
        float m = fmaxf(v0, v1);
#pragma unroll
        for (int off = 16; off; off >>= 1) m = fmaxf(m, __shfl_xor_sync(0xffffffffu, m, off));
        float e0 = __expf(v0 - m);
        float e1 = (lane < 17) ? __expf(v1 - m) : 0.f;
        float s = e0 + e1;
#pragma unroll
        for (int off = 16; off; off >>= 1) s += __shfl_xor_sync(0xffffffffu, s, off);
        const float inv = 1.f / s;
        Srow[lane] = __uint_as_float(f2tf32(e0 * inv));
        if (lane < 17)      Srow[lane + 32] = __uint_as_float(f2tf32(e1 * inv));
        else if (lane < 24) Srow[lane + 32] = 0.f;   // cols 49..55
    }
    __syncthreads();

    // ---- O = P V : per warp 1 m-tile x 8 n-tiles x 7 k-steps ----
    {
        const uint32_t* p32 = reinterpret_cast<const uint32_t*>(s_S);
        const uint32_t* v32 = reinterpret_cast<const uint32_t*>(s_v);
        float cO[8][4];
#pragma unroll
        for (int nt = 0; nt < 8; ++nt)
#pragma unroll
            for (int r = 0; r < 4; ++r) cO[nt][r] = 0.f;

#pragma unroll
        for (int k7 = 0; k7 < 7; ++k7) {
            const int j = k7 * 8;
            uint32_t a[4];
            a[0] = p32[(wr + g) * SST + j + tig];
            a[1] = p32[(wr + g + 8) * SST + j + tig];
            a[2] = p32[(wr + g) * SST + j + tig + 4];
            a[3] = p32[(wr + g + 8) * SST + j + tig + 4];
#pragma unroll
            for (int nt = 0; nt < 8; ++nt) {
                uint32_t bf[2];
                bf[0] = v32[(j + tig) * VS + nt * 8 + g];
                bf[1] = v32[(j + tig + 4) * VS + nt * 8 + g];
                mma_tf32(cO[nt], a, bf);
            }
        }

        const int r0 = wr + g;
        const int r1 = r0 + 8;
#pragma unroll
        for (int nt = 0; nt < 8; ++nt) {
            const int d = nt * 8 + 2 * tig;
            float* o0 = out + ((size_t)b * 256 + h * 64 + d) * HW;
            if (r0 < NTOK) {
                const int p = s_p[r0];
                if (partition == 0) { o0[p] = cO[nt][0];  o0[HW + p] = cO[nt][1]; }
                else                { o0[p] += cO[nt][0]; o0[HW + p] += cO[nt][1]; }
            }
            if (r1 < NTOK) {
                const int p = s_p[r1];
                if (partition == 0) { o0[p] = cO[nt][2];  o0[HW + p] = cO[nt][3]; }
                else                { o0[p] += cO[nt][2]; o0[HW + p] += cO[nt][3]; }
            }
        }
    }
}

// ---------------------------------------------------------------------------
extern "C" void kernel_launch(void* const* d_in, const int* in_sizes, int n_in,
                              void* d_out, int out_size)
{
    const float* x    = (const float*)d_in[0];
    const float* qk_w = (const float*)d_in[1];
    const float* v_w  = (const float*)d_in[2];
    float* out = (float*)d_out;

    const int conv_smem = 4 * ABUF * (int)sizeof(uint32_t);   // 69632 B
    cudaFuncSetAttribute(conv_kernel, cudaFuncAttributeMaxDynamicSharedMemorySize, conv_smem);
    conv_kernel<<<dim3(25, 6, 32), 256, conv_smem>>>(x, qk_w, v_w);

    cudaFuncSetAttribute(attn_kernel, cudaFuncAttributeMaxDynamicSharedMemorySize, ATTN_SMEM_BYTES);
    attn_kernel<<<dim3(64, 4, 32), 128, ATTN_SMEM_BYTES>>>(out, 0);  // remote: write
    attn_kernel<<<dim3(64, 4, 32), 128, ATTN_SMEM_BYTES>>>(out, 1);  // close: accumulate
}

// round 7
// speedup vs baseline: 4.5816x; 1.9010x over previous
#include <cuda_runtime.h>
#include <cstdint>
#include <cstddef>

#define BATCH 32
#define CIN   256
#define HW    3136
#define WIMG  56
#define NTOK  49
#define OCH   768

// Scratch: conv output, pixel-major [b][p][o] ; o: 0..511 = qk, 512..767 = v(relu)
__device__ float g_buf[(size_t)BATCH * HW * OCH];
// Attention output scratch, pixel-major [b][p][256], one per partition
__device__ float o_r[(size_t)BATCH * HW * 256];
__device__ float o_c[(size_t)BATCH * HW * 256];

__device__ __forceinline__ uint32_t f2tf32(float f) {
    uint32_t u;
    asm("cvt.rna.tf32.f32 %0, %1;" : "=r"(u) : "f"(f));
    return u;
}

__device__ __forceinline__ void mma_tf32(float* c, const uint32_t* a, const uint32_t* b) {
    asm volatile(
        "mma.sync.aligned.m16n8k8.row.col.f32.tf32.tf32.f32 "
        "{%0,%1,%2,%3}, {%4,%5,%6,%7}, {%8,%9}, {%0,%1,%2,%3};"
        : "+f"(c[0]), "+f"(c[1]), "+f"(c[2]), "+f"(c[3])
        : "r"(a[0]), "r"(a[1]), "r"(a[2]), "r"(a[3]), "r"(b[0]), "r"(b[1]));
}

// ---------------------------------------------------------------------------
// Kernel 1: fused 1x1 convs as tf32 tensor-core GEMM (unchanged)
// ---------------------------------------------------------------------------
#define KC     32
#define SPAD   136
#define ABUF   (KC * SPAD)

__global__ __launch_bounds__(256, 2) void conv_kernel(
    const float* __restrict__ x,
    const float* __restrict__ qk_w,
    const float* __restrict__ v_w)
{
    extern __shared__ uint32_t smem[];
    uint32_t* As = smem;
    uint32_t* Bs = smem + 2 * ABUF;

    const int b  = blockIdx.z;
    const int m0 = blockIdx.y * 128;
    const int n0 = blockIdx.x * 128;

    const int tid  = threadIdx.x;
    const int lane = tid & 31;
    const int wid  = tid >> 5;
    const int g    = lane >> 2;
    const int tig  = lane & 3;
    const int wm   = (wid >> 2) * 64;
    const int wn   = (wid & 3) * 32;

    const int mA = tid & 127;
    const int kq = tid >> 7;
    const int am = m0 + mA;
    const float* wptr = (am < 512) ? (qk_w + (size_t)am * 256)
                                   : (v_w + (size_t)(am - 512) * 256);
    const int nIdx = (tid & 31) * 4;
    const int kr   = tid >> 5;
    const int nB   = n0 + nIdx;
    const float* xptr = x + (size_t)b * CIN * HW + nB;
    const bool nOK = (nB < HW);

    float acc[4][4][4];
#pragma unroll
    for (int mm = 0; mm < 4; ++mm)
#pragma unroll
        for (int nn = 0; nn < 4; ++nn)
#pragma unroll
            for (int r = 0; r < 4; ++r) acc[mm][nn][r] = 0.f;

    float4 avr[4], bvr[4];
    auto load_chunk = [&](int k0) {
#pragma unroll
        for (int q = 0; q < 4; ++q)
            avr[q] = *reinterpret_cast<const float4*>(wptr + k0 + kq * 16 + q * 4);
#pragma unroll
        for (int j = 0; j < 4; ++j) {
            if (nOK) bvr[j] = *reinterpret_cast<const float4*>(xptr + (size_t)(k0 + kr + 8 * j) * HW);
            else     bvr[j] = make_float4(0.f, 0.f, 0.f, 0.f);
        }
    };
    auto store_chunk = [&](int buf) {
        uint32_t* Ab = As + buf * ABUF;
        uint32_t* Bb = Bs + buf * ABUF;
#pragma unroll
        for (int q = 0; q < 4; ++q) {
            const int kk = kq * 16 + q * 4;
            Ab[(kk + 0) * SPAD + mA] = f2tf32(avr[q].x);
            Ab[(kk + 1) * SPAD + mA] = f2tf32(avr[q].y);
            Ab[(kk + 2) * SPAD + mA] = f2tf32(avr[q].z);
            Ab[(kk + 3) * SPAD + mA] = f2tf32(avr[q].w);
        }
#pragma unroll
        for (int j = 0; j < 4; ++j) {
            uint32_t* d = Bb + (kr + 8 * j) * SPAD + nIdx;
            d[0] = f2tf32(bvr[j].x);
            d[1] = f2tf32(bvr[j].y);
            d[2] = f2tf32(bvr[j].z);
            d[3] = f2tf32(bvr[j].w);
        }
    };

    load_chunk(0);
    store_chunk(0);
    __syncthreads();

    int cur = 0;
    for (int k0 = 0; k0 < 256; k0 += KC) {
        const bool more = (k0 + KC < 256);
        if (more) load_chunk(k0 + KC);

        const uint32_t* Ab = As + cur * ABUF;
        const uint32_t* Bb = Bs + cur * ABUF;
#pragma unroll
        for (int kc = 0; kc < 4; ++kc) {
            const int k8 = kc * 8;
            uint32_t a[4][4], bb[4][2];
#pragma unroll
            for (int mm = 0; mm < 4; ++mm) {
                const int row = wm + mm * 16 + g;
                a[mm][0] = Ab[(k8 + tig) * SPAD + row];
                a[mm][1] = Ab[(k8 + tig) * SPAD + row + 8];
                a[mm][2] = Ab[(k8 + tig + 4) * SPAD + row];
                a[mm][3] = Ab[(k8 + tig + 4) * SPAD + row + 8];
            }
#pragma unroll
            for (int nn = 0; nn < 4; ++nn) {
                const int col = wn + nn * 8 + g;
                bb[nn][0] = Bb[(k8 + tig) * SPAD + col];
                bb[nn][1] = Bb[(k8 + tig + 4) * SPAD + col];
            }
#pragma unroll
            for (int mm = 0; mm < 4; ++mm)
#pragma unroll
                for (int nn = 0; nn < 4; ++nn)
                    mma_tf32(acc[mm][nn], a[mm], bb[nn]);
        }

        if (more) store_chunk(cur ^ 1);
        __syncthreads();
        cur ^= 1;
    }

    const bool isv = (m0 >= 512);
#pragma unroll
    for (int mm = 0; mm < 4; ++mm) {
#pragma unroll
        for (int nn = 0; nn < 4; ++nn) {
            const int ncol = n0 + wn + nn * 8 + 2 * tig;
            const int mrow = m0 + wm + mm * 16 + g;
            float v0 = acc[mm][nn][0];
            float v1 = acc[mm][nn][1];
            float v2 = acc[mm][nn][2];
            float v3 = acc[mm][nn][3];
            if (isv) {
                v0 = fmaxf(v0, 0.f); v1 = fmaxf(v1, 0.f);
                v2 = fmaxf(v2, 0.f); v3 = fmaxf(v3, 0.f);
            }
            if (ncol < HW) {
                float* d0 = g_buf + ((size_t)b * HW + ncol) * OCH + mrow;
                d0[0] = v0;
                d0[8] = v2;
            }
            if (ncol + 1 < HW) {
                float* d1 = g_buf + ((size_t)b * HW + ncol + 1) * OCH + mrow;
                d1[0] = v1;
                d1[8] = v3;
            }
        }
    }
}

// ---------------------------------------------------------------------------
// Kernel 2: tf32 tensor-core window attention, both partitions in one launch.
// Block = (win, h|part<<2, b), 128 threads = 4 warps, one m16 row-tile each.
// cp.async staging (MLP ~18). Raw f32 bits fed to mma.tf32 (HW truncation).
// Output written pixel-major to o_r / o_c (fully coalesced 32B chunks).
// ---------------------------------------------------------------------------
#define QS 68
#define VS 72
#define SST 60

#define OFF_Q 0
#define OFF_K (OFF_Q + 64 * QS)
#define OFF_V (OFF_K + 56 * QS)
#define OFF_S (OFF_V + 56 * VS)
#define OFF_P (OFF_S + 64 * SST)
#define ATTN_SMEM_BYTES ((OFF_P + NTOK) * 4 + 12)

__global__ __launch_bounds__(128) void attn_kernel()
{
    extern __shared__ float sm[];
    float* s_q = sm + OFF_Q;
    float* s_k = sm + OFF_K;
    float* s_v = sm + OFF_V;
    float* s_S = sm + OFF_S;
    int*   s_p = reinterpret_cast<int*>(sm + OFF_P);

    const int b    = blockIdx.z;
    const int h    = blockIdx.y & 3;
    const int part = blockIdx.y >> 2;
    const int win  = blockIdx.x;
    const int j1   = win >> 3;
    const int j2   = win & 7;
    const int tid  = threadIdx.x;
    const int lane = tid & 31;
    const int wid  = tid >> 5;
    const int g    = lane >> 2;
    const int tig  = lane & 3;
    const int wr   = wid * 16;

    if (tid < NTOK) {
        int h1 = tid / 7, w1 = tid - h1 * 7;
        int hh, ww;
        if (part == 0) { hh = h1 * 8 + j1; ww = w1 * 8 + j2; }   // remote
        else           { hh = j1 * 7 + h1; ww = j2 * 7 + w1; }   // close
        s_p[tid] = hh * WIMG + ww;
    }
    // zero V pad rows (P pad cols are exact zeros, but NaN*0 = NaN -> must zero)
    for (int i = tid; i < 7 * VS; i += 128) s_v[49 * VS + i] = 0.f;
    __syncthreads();

    // ---- stage q,k,v via cp.async: 49 pixels x 3 segs x 16 float4 ----
    {
        const float* base = g_buf + (size_t)b * HW * OCH + h * 64;
        for (int idx = tid; idx < NTOK * 48; idx += 128) {
            const int pix = idx / 48;
            const int r   = idx - pix * 48;
            const int seg = r >> 4;          // 0=q,1=k,2=v
            const int d4  = r & 15;
            const float* src = base + (size_t)s_p[pix] * OCH + seg * 256 + d4 * 4;
            float* dstf = (seg == 0 ? s_q + pix * QS
                         : seg == 1 ? s_k + pix * QS
                                    : s_v + pix * VS) + d4 * 4;
            uint32_t dsta = (uint32_t)__cvta_generic_to_shared(dstf);
            asm volatile("cp.async.ca.shared.global [%0], [%1], 16;\n"
                         :: "r"(dsta), "l"(src));
        }
        asm volatile("cp.async.commit_group;\n");
        asm volatile("cp.async.wait_group 0;\n" ::: "memory");
    }
    __syncthreads();

    // ---- S = Q K^T * scale ----
    {
        const uint32_t* q32 = reinterpret_cast<const uint32_t*>(s_q);
        const uint32_t* k32 = reinterpret_cast<const uint32_t*>(s_k);
        float cS[7][4];
#pragma unroll
        for (int nt = 0; nt < 7; ++nt)
#pragma unroll
            for (int r = 0; r < 4; ++r) cS[nt][r] = 0.f;

#pragma unroll
        for (int k8 = 0; k8 < 8; ++k8) {
            const int k = k8 * 8;
            uint32_t a[4];
            a[0] = q32[(wr + g) * QS + k + tig];
            a[1] = q32[(wr + g + 8) * QS + k + tig];
            a[2] = q32[(wr + g) * QS + k + tig + 4];
            a[3] = q32[(wr + g + 8) * QS + k + tig + 4];
#pragma unroll
            for (int nt = 0; nt < 7; ++nt) {
                uint32_t bf[2];
                bf[0] = k32[(nt * 8 + g) * QS + k + tig];
                bf[1] = k32[(nt * 8 + g) * QS + k + tig + 4];
                mma_tf32(cS[nt], a, bf);
            }
        }
#pragma unroll
        for (int nt = 0; nt < 7; ++nt) {
            float* S0 = s_S + (wr + g) * SST + nt * 8 + 2 * tig;
            float* S1 = s_S + (wr + g + 8) * SST + nt * 8 + 2 * tig;
            S0[0] = cS[nt][0] * 0.125f;
            S0[1] = cS[nt][1] * 0.125f;
            S1[0] = cS[nt][2] * 0.125f;
            S1[1] = cS[nt][3] * 0.125f;
        }
    }
    __syncthreads();

    // ---- softmax rows 0..48; zero pad cols 49..55 ----
    for (int row = wid; row < NTOK; row += 4) {
        float* Srow = s_S + row * SST;
        float v0 = Srow[lane];
        float v1 = (lane < 17) ? Srow[lane + 32] : -3.0e38f;
        float m = fmaxf(v0, v1);
#pragma unroll
        for (int off = 16; off; off >>= 1) m = fmaxf(m, __shfl_xor_sync(0xffffffffu, m, off));
        float e0 = __expf(v0 - m);
        float e1 = (lane < 17) ? __expf(v1 - m) : 0.f;
        float s = e0 + e1;
#pragma unroll
        for (int off = 16; off; off >>= 1) s += __shfl_xor_sync(0xffffffffu, s, off);
        const float inv = 1.f / s;
        Srow[lane] = e0 * inv;
        if (lane < 17)      Srow[lane + 32] = e1 * inv;
        else if (lane < 24) Srow[lane + 32] = 0.f;   // cols 49..55
    }
    __syncthreads();

    // ---- O = P V ----
    {
        const uint32_t* p32 = reinterpret_cast<const uint32_t*>(s_S);
        const uint32_t* v32 = reinterpret_cast<const uint32_t*>(s_v);
        float cO[8][4];
#pragma unroll
        for (int nt = 0; nt < 8; ++nt)
#pragma unroll
            for (int r = 0; r < 4; ++r) cO[nt][r] = 0.f;

#pragma unroll
        for (int k7 = 0; k7 < 7; ++k7) {
            const int j = k7 * 8;
            uint32_t a[4];
            a[0] = p32[(wr + g) * SST + j + tig];
            a[1] = p32[(wr + g + 8) * SST + j + tig];
            a[2] = p32[(wr + g) * SST + j + tig + 4];
            a[3] = p32[(wr + g + 8) * SST + j + tig + 4];
#pragma unroll
            for (int nt = 0; nt < 8; ++nt) {
                uint32_t bf[2];
                bf[0] = v32[(j + tig) * VS + nt * 8 + g];
                bf[1] = v32[(j + tig + 4) * VS + nt * 8 + g];
                mma_tf32(cO[nt], a, bf);
            }
        }

        float* obuf = (part == 0) ? o_r : o_c;
        const int r0 = wr + g;
        const int r1 = r0 + 8;
#pragma unroll
        for (int nt = 0; nt < 8; ++nt) {
            const int d = h * 64 + nt * 8 + 2 * tig;
            if (r0 < NTOK) {
                float2 val = make_float2(cO[nt][0], cO[nt][1]);
                *reinterpret_cast<float2*>(&obuf[((size_t)b * HW + s_p[r0]) * 256 + d]) = val;
            }
            if (r1 < NTOK) {
                float2 val = make_float2(cO[nt][2], cO[nt][3]);
                *reinterpret_cast<float2*>(&obuf[((size_t)b * HW + s_p[r1]) * 256 + d]) = val;
            }
        }
    }
}

// ---------------------------------------------------------------------------
// Kernel 3: merge + transpose: out[b][c][p] = o_r[b][p][c] + o_c[b][p][c]
// ---------------------------------------------------------------------------
__global__ __launch_bounds__(256) void merge_kernel(float* __restrict__ out)
{
    __shared__ float tile[32][33];
    const int b  = blockIdx.z;
    const int c0 = blockIdx.y * 32;
    const int p0 = blockIdx.x * 32;
    const int tx = threadIdx.x & 31;
    const int ty = threadIdx.x >> 5;

#pragma unroll
    for (int i = 0; i < 4; ++i) {
        const int p = p0 + ty + i * 8;
        const size_t off = ((size_t)b * HW + p) * 256 + c0 + tx;
        tile[ty + i * 8][tx] = o_r[off] + o_c[off];
    }
    __syncthreads();
#pragma unroll
    for (int i = 0; i < 4; ++i) {
        const int c = c0 + ty + i * 8;
        out[((size_t)b * 256 + c) * HW + p0 + tx] = tile[tx][ty + i * 8];
    }
}

// ---------------------------------------------------------------------------
extern "C" void kernel_launch(void* const* d_in, const int* in_sizes, int n_in,
                              void* d_out, int out_size)
{
    const float* x    = (const float*)d_in[0];
    const float* qk_w = (const float*)d_in[1];
    const float* v_w  = (const float*)d_in[2];
    float* out = (float*)d_out;

    const int conv_smem = 4 * ABUF * (int)sizeof(uint32_t);   // 69632 B
    cudaFuncSetAttribute(conv_kernel, cudaFuncAttributeMaxDynamicSharedMemorySize, conv_smem);
    conv_kernel<<<dim3(25, 6, 32), 256, conv_smem>>>(x, qk_w, v_w);

    cudaFuncSetAttribute(attn_kernel, cudaFuncAttributeMaxDynamicSharedMemorySize, ATTN_SMEM_BYTES);
    attn_kernel<<<dim3(64, 8, 32), 128, ATTN_SMEM_BYTES>>>();

    merge_kernel<<<dim3(98, 8, 32), 256>>>(out);
}